// round 5
// baseline (speedup 1.0000x reference)
#include <cuda_runtime.h>
#include <cuda_bf16.h>
#include <stdint.h>

// Problem constants
#define NIN   1024
#define NHEAD 16
#define HDIM  64
#define BATCH 2
#define SEQ   2048
#define MTOT  4096
#define BH    (BATCH * NHEAD)   // 32

// ---------------------------------------------------------------------------
// Device-global scratch (bf16 hi/lo everywhere; no fp32 intermediates)
// ---------------------------------------------------------------------------
__device__ __align__(128) __nv_bfloat16 g_xh[MTOT * NIN];
__device__ __align__(128) __nv_bfloat16 g_xl[MTOT * NIN];
__device__ __align__(128) __nv_bfloat16 g_wh[4 * NIN * NIN];
__device__ __align__(128) __nv_bfloat16 g_wl[4 * NIN * NIN];
__device__ __align__(128) __nv_bfloat16 g_qh[BH * SEQ * HDIM];
__device__ __align__(128) __nv_bfloat16 g_ql[BH * SEQ * HDIM];
__device__ __align__(128) __nv_bfloat16 g_kh[BH * SEQ * HDIM];
__device__ __align__(128) __nv_bfloat16 g_kl[BH * SEQ * HDIM];
__device__ __align__(128) __nv_bfloat16 g_vth[BH * HDIM * SEQ];  // [bh][d][s]
__device__ __align__(128) __nv_bfloat16 g_vtl[BH * HDIM * SEQ];
__device__ __align__(128) __nv_bfloat16 g_ath[MTOT * NIN];
__device__ __align__(128) __nv_bfloat16 g_atl[MTOT * NIN];

// ---------------------------------------------------------------------------
// Helpers (sm_80-level only: cp.async, mma.sync, ldmatrix)
// ---------------------------------------------------------------------------
__device__ __forceinline__ uint32_t smem_u32(const void* p) {
    uint32_t a;
    asm("{ .reg .u64 t; cvta.to.shared.u64 t, %1; cvt.u32.u64 %0, t; }" : "=r"(a) : "l"(p));
    return a;
}
__device__ __forceinline__ void cp16(uint32_t dst, const void* src) {
    asm volatile("cp.async.cg.shared.global [%0], [%1], 16;" :: "r"(dst), "l"(src));
}
#define CP_COMMIT() asm volatile("cp.async.commit_group;" ::: "memory")
#define CP_WAIT(n)  asm volatile("cp.async.wait_group %0;" :: "n"(n) : "memory")

__device__ __forceinline__ void sts32(uint32_t addr, uint32_t v) {
    asm volatile("st.shared.b32 [%0], %1;" :: "r"(addr), "r"(v));
}
__device__ __forceinline__ void ldm_x4(uint32_t (&r)[4], uint32_t addr) {
    asm volatile("ldmatrix.sync.aligned.m8n8.x4.shared.b16 {%0,%1,%2,%3}, [%4];"
                 : "=r"(r[0]), "=r"(r[1]), "=r"(r[2]), "=r"(r[3]) : "r"(addr));
}

// m16n8k16 bf16 MMA, fp32 accum
__device__ __forceinline__ void mma_bf16(float (&c)[4], const uint32_t (&a)[4],
                                         uint32_t b0, uint32_t b1) {
    asm volatile(
        "mma.sync.aligned.m16n8k16.row.col.f32.bf16.bf16.f32 "
        "{%0,%1,%2,%3}, {%4,%5,%6,%7}, {%8,%9}, {%0,%1,%2,%3};"
        : "+f"(c[0]), "+f"(c[1]), "+f"(c[2]), "+f"(c[3])
        : "r"(a[0]), "r"(a[1]), "r"(a[2]), "r"(a[3]), "r"(b0), "r"(b1));
}

__device__ __forceinline__ void split_pack(float x, float y, uint32_t& h, uint32_t& l) {
    __nv_bfloat16 hx = __float2bfloat16(x), hy = __float2bfloat16(y);
    __nv_bfloat16 lx = __float2bfloat16(x - __bfloat162float(hx));
    __nv_bfloat16 ly = __float2bfloat16(y - __bfloat162float(hy));
    __nv_bfloat162 hp, lp;
    hp.x = hx; hp.y = hy; lp.x = lx; lp.y = ly;
    h = *(uint32_t*)&hp; l = *(uint32_t*)&lp;
}

// ---------------------------------------------------------------------------
// fp32 -> bf16 hi/lo split (inputs only: x and the four W's)
// ---------------------------------------------------------------------------
__global__ __launch_bounds__(256) void split_kernel(const float* __restrict__ src,
                                                    __nv_bfloat16* __restrict__ hi,
                                                    __nv_bfloat16* __restrict__ lo, int n4) {
    int i = blockIdx.x * 256 + threadIdx.x;
    if (i >= n4) return;
    float4 v = ((const float4*)src)[i];
    uint32_t h0, l0, h1, l1;
    split_pack(v.x, v.y, h0, l0);
    split_pack(v.z, v.w, h1, l1);
    uint2 uh, ul;
    uh.x = h0; uh.y = h1; ul.x = l0; ul.y = l1;
    ((uint2*)hi)[i] = uh;
    ((uint2*)lo)[i] = ul;
}

// ---------------------------------------------------------------------------
// Projection GEMM body: C[m][n] = sum_k A[m][k] * W[n][k]  (3-term bf16 hi/lo)
// CTA 128x128, 8 warps (2m x 4n), warp 64x32. K-chunk 32, double-buffered.
// ---------------------------------------------------------------------------
#define P_ROWB   80
#define P_OFF_AH 0
#define P_OFF_AL (128 * P_ROWB)
#define P_OFF_BH (2 * 128 * P_ROWB)
#define P_OFF_BL (3 * 128 * P_ROWB)
#define P_STAGE  (4 * 128 * P_ROWB)          // 40960
#define GEMM_SMEM (2 * P_STAGE)              // 81920

__device__ __forceinline__ void proj_load_chunk(
    const __nv_bfloat16* __restrict__ Ah, const __nv_bfloat16* __restrict__ Al,
    const __nv_bfloat16* __restrict__ Bh, const __nv_bfloat16* __restrict__ Bl,
    int mBase, int nBase, int k0, uint32_t st)
{
    const int tid = threadIdx.x;
#pragma unroll
    for (int idx = tid; idx < 512; idx += 256) {
        const int row = idx >> 2, seg = idx & 3;
        const size_t ga = (size_t)(mBase + row) * NIN + k0 + seg * 8;
        const size_t gb = (size_t)(nBase + row) * NIN + k0 + seg * 8;
        const uint32_t so = row * P_ROWB + seg * 16;
        cp16(st + P_OFF_AH + so, Ah + ga);
        cp16(st + P_OFF_AL + so, Al + ga);
        cp16(st + P_OFF_BH + so, Bh + gb);
        cp16(st + P_OFF_BL + so, Bl + gb);
    }
}

__device__ __forceinline__ void gemm_body(
    const __nv_bfloat16* Ah, const __nv_bfloat16* Al,
    const __nv_bfloat16* Bh, const __nv_bfloat16* Bl,
    int mBase, int nBase, char* smem, float C[4][4][4])
{
    const uint32_t sb = smem_u32(smem);
    const int tid = threadIdx.x;
    const int wid = tid >> 5, lane = tid & 31;
    const int wm = wid >> 2, wn = wid & 3;

    // ldmatrix lane address components
    const uint32_t aRow = lane & 15;                            // A rows 0..15
    const uint32_t aCol = (lane >> 4) << 4;                     // +0/+16 bytes
    const uint32_t bRow = (lane & 7) | ((lane >> 1) & 8);       // B rows 0..15
    const uint32_t bCol = ((lane >> 3) & 1) << 4;               // +0/+16 bytes

#pragma unroll
    for (int a = 0; a < 4; a++)
#pragma unroll
        for (int b = 0; b < 4; b++)
#pragma unroll
            for (int c = 0; c < 4; c++) C[a][b][c] = 0.f;

    proj_load_chunk(Ah, Al, Bh, Bl, mBase, nBase, 0, sb);
    CP_COMMIT();

    for (int i = 0; i < 32; i++) {
        if (i < 31) {
            proj_load_chunk(Ah, Al, Bh, Bl, mBase, nBase, (i + 1) * 32,
                            sb + ((i + 1) & 1) * P_STAGE);
            CP_COMMIT();
            CP_WAIT(1);
        } else {
            CP_WAIT(0);
        }
        __syncthreads();

        const uint32_t st = sb + (i & 1) * P_STAGE;
#pragma unroll
        for (int ks = 0; ks < 2; ks++) {
            const uint32_t cb = ks * 32;
            uint32_t ah[4][4], al[4][4];
#pragma unroll
            for (int mt = 0; mt < 4; mt++) {
                const uint32_t ra = st + (wm * 64 + mt * 16 + aRow) * P_ROWB + cb + aCol;
                ldm_x4(ah[mt], ra + P_OFF_AH);
                ldm_x4(al[mt], ra + P_OFF_AL);
            }
#pragma unroll
            for (int p = 0; p < 2; p++) {
                const uint32_t rb = st + (wn * 32 + p * 16 + bRow) * P_ROWB + cb + bCol;
                uint32_t bhf[4], blf[4];
                ldm_x4(bhf, rb + P_OFF_BH);
                ldm_x4(blf, rb + P_OFF_BL);
#pragma unroll
                for (int mt = 0; mt < 4; mt++) {
                    mma_bf16(C[mt][2 * p], ah[mt], bhf[0], bhf[1]);
                    mma_bf16(C[mt][2 * p], ah[mt], blf[0], blf[1]);
                    mma_bf16(C[mt][2 * p], al[mt], bhf[0], bhf[1]);
                    mma_bf16(C[mt][2 * p + 1], ah[mt], bhf[2], bhf[3]);
                    mma_bf16(C[mt][2 * p + 1], ah[mt], blf[2], blf[3]);
                    mma_bf16(C[mt][2 * p + 1], al[mt], bhf[2], bhf[3]);
                }
            }
        }
        __syncthreads();
    }
}

// QKV projection: fused split epilogues. grid (8, 32, 3)
__global__ __launch_bounds__(256) void qkv_tc_kernel(
    const float* __restrict__ bq, const float* __restrict__ bk, const float* __restrict__ bv)
{
    extern __shared__ char smem[];
    const int z = blockIdx.z;
    const __nv_bfloat16* Wh = g_wh + (size_t)z * NIN * NIN;
    const __nv_bfloat16* Wl = g_wl + (size_t)z * NIN * NIN;
    const float* bias = (z == 0) ? bq : (z == 1) ? bk : bv;

    const int mBase = blockIdx.y * 128;
    const int nBase = blockIdx.x * 128;

    float C[4][4][4];
    gemm_body(g_xh, g_xl, Wh, Wl, mBase, nBase, smem, C);

    const int tid = threadIdx.x, wid = tid >> 5, lane = tid & 31;
    const int g = lane >> 2, t4 = lane & 3;
    const int wm = wid >> 2, wn = wid & 3;

    __nv_bfloat16* dh = (z == 0) ? g_qh : g_kh;
    __nv_bfloat16* dl = (z == 0) ? g_ql : g_kl;

#pragma unroll
    for (int mt = 0; mt < 4; mt++) {
        const int m0 = mBase + wm * 64 + mt * 16 + g;
        const int m1 = m0 + 8;
        const int b0 = m0 >> 11, nr0 = m0 & 2047;
        const int b1 = m1 >> 11, nr1 = m1 & 2047;
#pragma unroll
        for (int nt = 0; nt < 4; nt++) {
            const int n = nBase + wn * 32 + nt * 8 + t4 * 2;
            const int h = n >> 6, d = n & 63;
            const float2 bb = *(const float2*)(bias + n);
            const float v00 = C[mt][nt][0] + bb.x, v01 = C[mt][nt][1] + bb.y;
            const float v10 = C[mt][nt][2] + bb.x, v11 = C[mt][nt][3] + bb.y;
            if (z != 2) {
                uint32_t h0, l0, h1, l1;
                split_pack(v00, v01, h0, l0);
                split_pack(v10, v11, h1, l1);
                const size_t o0 = ((size_t)(b0 * NHEAD + h) * SEQ + nr0) * HDIM + d;
                const size_t o1 = ((size_t)(b1 * NHEAD + h) * SEQ + nr1) * HDIM + d;
                *(uint32_t*)(dh + o0) = h0; *(uint32_t*)(dl + o0) = l0;
                *(uint32_t*)(dh + o1) = h1; *(uint32_t*)(dl + o1) = l1;
            } else {
                // V: transposed [bh][d][s] scatter
                const size_t base0 = ((size_t)(b0 * NHEAD + h) * HDIM + d) * SEQ;
                const size_t base1 = ((size_t)(b1 * NHEAD + h) * HDIM + d) * SEQ;
                uint32_t h0, l0, h1, l1;
                split_pack(v00, v10, h0, l0);   // pair along m is NOT contiguous; store scalars
                split_pack(v01, v11, h1, l1);
                __nv_bfloat162 hp0 = *(__nv_bfloat162*)&h0, lp0 = *(__nv_bfloat162*)&l0;
                __nv_bfloat162 hp1 = *(__nv_bfloat162*)&h1, lp1 = *(__nv_bfloat162*)&l1;
                g_vth[base0 + nr0] = hp0.x;  g_vtl[base0 + nr0] = lp0.x;
                g_vth[base1 + nr1] = hp0.y;  g_vtl[base1 + nr1] = lp0.y;
                g_vth[base0 + SEQ + nr0] = hp1.x;  g_vtl[base0 + SEQ + nr0] = lp1.x;
                g_vth[base1 + SEQ + nr1] = hp1.y;  g_vtl[base1 + SEQ + nr1] = lp1.y;
            }
        }
    }
}

// O projection: grid (8, 32)
__global__ __launch_bounds__(256) void out_tc_kernel(
    const float* __restrict__ bo, float* __restrict__ out)
{
    extern __shared__ char smem[];
    const int mBase = blockIdx.y * 128;
    const int nBase = blockIdx.x * 128;

    float C[4][4][4];
    gemm_body(g_ath, g_atl, g_wh + 3 * NIN * NIN, g_wl + 3 * NIN * NIN,
              mBase, nBase, smem, C);

    const int tid = threadIdx.x, wid = tid >> 5, lane = tid & 31;
    const int g = lane >> 2, t4 = lane & 3;
    const int wm = wid >> 2, wn = wid & 3;

#pragma unroll
    for (int mt = 0; mt < 4; mt++) {
        const int m0 = mBase + wm * 64 + mt * 16 + g;
#pragma unroll
        for (int nt = 0; nt < 4; nt++) {
            const int n = nBase + wn * 32 + nt * 8 + t4 * 2;
            const float2 bb = *(const float2*)(bo + n);
            *(float2*)(out + (size_t)m0 * NIN + n) =
                make_float2(C[mt][nt][0] + bb.x, C[mt][nt][1] + bb.y);
            *(float2*)(out + (size_t)(m0 + 8) * NIN + n) =
                make_float2(C[mt][nt][2] + bb.x, C[mt][nt][3] + bb.y);
        }
    }
}

// ---------------------------------------------------------------------------
// Tensor-core flash attention (ldmatrix fragments, fused output split).
// CTA: 128 q rows (8 warps x 16), kv chunks of 64, 3-term bf16 hi/lo.
// ---------------------------------------------------------------------------
#define A_ROWB    144
#define A_KV      (64 * A_ROWB)
#define A_OFF_KH  0
#define A_OFF_KL  (2 * A_KV)
#define A_OFF_VH  (4 * A_KV)
#define A_OFF_VL  (6 * A_KV)
#define A_OFF_PH  (8 * A_KV)
#define A_OFF_PL  (A_OFF_PH + 8 * 16 * A_ROWB)
#define ATT_SMEM  (A_OFF_PL + 8 * 16 * A_ROWB)   // 110592

__global__ __launch_bounds__(256) void attn_tc_kernel()
{
    extern __shared__ char smem[];
    const uint32_t sb = smem_u32(smem);
    const int tid = threadIdx.x;
    const int w = tid >> 5, lane = tid & 31;
    const int g = lane >> 2, t4 = lane & 3;
    const int bh = blockIdx.y;
    const int q0 = blockIdx.x * 128;

    const __nv_bfloat16* Qh = g_qh + (size_t)bh * SEQ * HDIM;
    const __nv_bfloat16* Ql = g_ql + (size_t)bh * SEQ * HDIM;
    const __nv_bfloat16* Khg = g_kh + (size_t)bh * SEQ * HDIM;
    const __nv_bfloat16* Klg = g_kl + (size_t)bh * SEQ * HDIM;
    const __nv_bfloat16* Vhg = g_vth + (size_t)bh * HDIM * SEQ;
    const __nv_bfloat16* Vlg = g_vtl + (size_t)bh * HDIM * SEQ;

    // ldmatrix lane address components
    const uint32_t aRow = lane & 15;
    const uint32_t aCol = (lane >> 4) << 4;
    const uint32_t bRow = (lane & 7) | ((lane >> 1) & 8);
    const uint32_t bCol = ((lane >> 3) & 1) << 4;

    // --- Q fragments direct from global (bf16 pairs) ---
    const int r0 = q0 + w * 16 + g, r1 = r0 + 8;
    uint32_t qh[4][4], ql[4][4];
#pragma unroll
    for (int ks = 0; ks < 4; ks++) {
        const int c = ks * 16 + t4 * 2;
        qh[ks][0] = *(const uint32_t*)(Qh + (size_t)r0 * HDIM + c);
        qh[ks][1] = *(const uint32_t*)(Qh + (size_t)r1 * HDIM + c);
        qh[ks][2] = *(const uint32_t*)(Qh + (size_t)r0 * HDIM + c + 8);
        qh[ks][3] = *(const uint32_t*)(Qh + (size_t)r1 * HDIM + c + 8);
        ql[ks][0] = *(const uint32_t*)(Ql + (size_t)r0 * HDIM + c);
        ql[ks][1] = *(const uint32_t*)(Ql + (size_t)r1 * HDIM + c);
        ql[ks][2] = *(const uint32_t*)(Ql + (size_t)r0 * HDIM + c + 8);
        ql[ks][3] = *(const uint32_t*)(Ql + (size_t)r1 * HDIM + c + 8);
    }

    float O[8][4];
#pragma unroll
    for (int nt = 0; nt < 8; nt++)
#pragma unroll
        for (int c = 0; c < 4; c++) O[nt][c] = 0.f;
    float mrow0 = -1e30f, mrow1 = -1e30f, lrow0 = 0.f, lrow1 = 0.f;

    const uint32_t pwh = sb + A_OFF_PH + w * 16 * A_ROWB;
    const uint32_t pwl = sb + A_OFF_PL + w * 16 * A_ROWB;

    auto load_kv = [&](int k0, int st) {
#pragma unroll
        for (int idx = tid; idx < 512; idx += 256) {
            const int row = idx >> 3, seg = idx & 7;
            const uint32_t so = st * A_KV + row * A_ROWB + seg * 16;
            cp16(sb + A_OFF_KH + so, Khg + (size_t)(k0 + row) * HDIM + seg * 8);
            cp16(sb + A_OFF_KL + so, Klg + (size_t)(k0 + row) * HDIM + seg * 8);
            cp16(sb + A_OFF_VH + so, Vhg + (size_t)row * SEQ + k0 + seg * 8);
            cp16(sb + A_OFF_VL + so, Vlg + (size_t)row * SEQ + k0 + seg * 8);
        }
    };

    load_kv(0, 0);
    CP_COMMIT();

    for (int i = 0; i < SEQ / 64; i++) {
        if (i < SEQ / 64 - 1) {
            load_kv((i + 1) * 64, (i + 1) & 1);
            CP_COMMIT();
            CP_WAIT(1);
        } else {
            CP_WAIT(0);
        }
        __syncthreads();

        const uint32_t stK = sb + (i & 1) * A_KV;

        // ---- S = Q K^T (3-term) ----
        float S[8][4];
#pragma unroll
        for (int nt = 0; nt < 8; nt++)
#pragma unroll
            for (int c = 0; c < 4; c++) S[nt][c] = 0.f;

#pragma unroll
        for (int ks = 0; ks < 4; ks++) {
            const uint32_t cb = ks * 32;
#pragma unroll
            for (int p = 0; p < 4; p++) {
                const uint32_t rb = stK + (p * 16 + bRow) * A_ROWB + cb + bCol;
                uint32_t khf[4], klf[4];
                ldm_x4(khf, rb + A_OFF_KH);
                ldm_x4(klf, rb + A_OFF_KL);
                mma_bf16(S[2 * p], qh[ks], khf[0], khf[1]);
                mma_bf16(S[2 * p], qh[ks], klf[0], klf[1]);
                mma_bf16(S[2 * p], ql[ks], khf[0], khf[1]);
                mma_bf16(S[2 * p + 1], qh[ks], khf[2], khf[3]);
                mma_bf16(S[2 * p + 1], qh[ks], klf[2], klf[3]);
                mma_bf16(S[2 * p + 1], ql[ks], khf[2], khf[3]);
            }
        }

        // ---- online softmax ----
        float mx0 = -1e30f, mx1 = -1e30f;
#pragma unroll
        for (int nt = 0; nt < 8; nt++) {
#pragma unroll
            for (int c = 0; c < 4; c++) S[nt][c] *= 0.125f;
            mx0 = fmaxf(mx0, fmaxf(S[nt][0], S[nt][1]));
            mx1 = fmaxf(mx1, fmaxf(S[nt][2], S[nt][3]));
        }
        mx0 = fmaxf(mx0, __shfl_xor_sync(0xffffffffu, mx0, 1));
        mx0 = fmaxf(mx0, __shfl_xor_sync(0xffffffffu, mx0, 2));
        mx1 = fmaxf(mx1, __shfl_xor_sync(0xffffffffu, mx1, 1));
        mx1 = fmaxf(mx1, __shfl_xor_sync(0xffffffffu, mx1, 2));

        const float mn0 = fmaxf(mrow0, mx0), mn1 = fmaxf(mrow1, mx1);
        const float cr0 = __expf(mrow0 - mn0), cr1 = __expf(mrow1 - mn1);
        mrow0 = mn0; mrow1 = mn1;

        float rs0 = 0.f, rs1 = 0.f;
#pragma unroll
        for (int nt = 0; nt < 8; nt++) {
            const float p00 = __expf(S[nt][0] - mn0);
            const float p01 = __expf(S[nt][1] - mn0);
            const float p10 = __expf(S[nt][2] - mn1);
            const float p11 = __expf(S[nt][3] - mn1);
            rs0 += p00 + p01;
            rs1 += p10 + p11;
            uint32_t h0, l0, h1, l1;
            split_pack(p00, p01, h0, l0);
            split_pack(p10, p11, h1, l1);
            const uint32_t cbyte = nt * 16 + t4 * 4;
            sts32(pwh + g * A_ROWB + cbyte, h0);
            sts32(pwl + g * A_ROWB + cbyte, l0);
            sts32(pwh + (g + 8) * A_ROWB + cbyte, h1);
            sts32(pwl + (g + 8) * A_ROWB + cbyte, l1);
        }
        rs0 += __shfl_xor_sync(0xffffffffu, rs0, 1);
        rs0 += __shfl_xor_sync(0xffffffffu, rs0, 2);
        rs1 += __shfl_xor_sync(0xffffffffu, rs1, 1);
        rs1 += __shfl_xor_sync(0xffffffffu, rs1, 2);
        lrow0 = lrow0 * cr0 + rs0;
        lrow1 = lrow1 * cr1 + rs1;
#pragma unroll
        for (int nt = 0; nt < 8; nt++) {
            O[nt][0] *= cr0; O[nt][1] *= cr0;
            O[nt][2] *= cr1; O[nt][3] *= cr1;
        }
        __syncwarp();

        // ---- O += P V (3-term) ----
#pragma unroll
        for (int ks = 0; ks < 4; ks++) {
            const uint32_t cb = ks * 32;
            uint32_t pah[4], pal[4];
            ldm_x4(pah, pwh + aRow * A_ROWB + cb + aCol);
            ldm_x4(pal, pwl + aRow * A_ROWB + cb + aCol);
#pragma unroll
            for (int p = 0; p < 4; p++) {
                const uint32_t rv = stK + (p * 16 + bRow) * A_ROWB + cb + bCol;
                uint32_t vhf[4], vlf[4];
                ldm_x4(vhf, rv + A_OFF_VH);
                ldm_x4(vlf, rv + A_OFF_VL);
                mma_bf16(O[2 * p], pah, vhf[0], vhf[1]);
                mma_bf16(O[2 * p], pah, vlf[0], vlf[1]);
                mma_bf16(O[2 * p], pal, vhf[0], vhf[1]);
                mma_bf16(O[2 * p + 1], pah, vhf[2], vhf[3]);
                mma_bf16(O[2 * p + 1], pah, vlf[2], vlf[3]);
                mma_bf16(O[2 * p + 1], pal, vhf[2], vhf[3]);
            }
        }
        __syncthreads();
    }

    // ---- normalize, split, write ath/atl in [B,N,C] ----
    const float inv0 = 1.f / lrow0, inv1 = 1.f / lrow1;
    const int b = bh >> 4, h = bh & 15;
    const size_t o0 = ((size_t)(b * SEQ + r0) * NIN) + h * HDIM;
    const size_t o1 = ((size_t)(b * SEQ + r1) * NIN) + h * HDIM;
#pragma unroll
    for (int nt = 0; nt < 8; nt++) {
        const int col = nt * 8 + t4 * 2;
        uint32_t h0, l0, h1, l1;
        split_pack(O[nt][0] * inv0, O[nt][1] * inv0, h0, l0);
        split_pack(O[nt][2] * inv1, O[nt][3] * inv1, h1, l1);
        *(uint32_t*)(g_ath + o0 + col) = h0;
        *(uint32_t*)(g_atl + o0 + col) = l0;
        *(uint32_t*)(g_ath + o1 + col) = h1;
        *(uint32_t*)(g_atl + o1 + col) = l1;
    }
}

// ---------------------------------------------------------------------------
// Launch
// ---------------------------------------------------------------------------
extern "C" void kernel_launch(void* const* d_in, const int* in_sizes, int n_in,
                              void* d_out, int out_size)
{
    (void)in_sizes; (void)n_in; (void)out_size;
    const float* x  = (const float*)d_in[0];
    const float* Wq = (const float*)d_in[1];
    const float* bq = (const float*)d_in[2];
    const float* Wk = (const float*)d_in[3];
    const float* bk = (const float*)d_in[4];
    const float* Wv = (const float*)d_in[5];
    const float* bv = (const float*)d_in[6];
    const float* Wo = (const float*)d_in[7];
    const float* bo = (const float*)d_in[8];
    float* out = (float*)d_out;

    void* p;
    cudaGetSymbolAddress(&p, g_xh);  __nv_bfloat16* xh = (__nv_bfloat16*)p;
    cudaGetSymbolAddress(&p, g_xl);  __nv_bfloat16* xl = (__nv_bfloat16*)p;
    cudaGetSymbolAddress(&p, g_wh);  __nv_bfloat16* wh = (__nv_bfloat16*)p;
    cudaGetSymbolAddress(&p, g_wl);  __nv_bfloat16* wl = (__nv_bfloat16*)p;

    cudaFuncSetAttribute(qkv_tc_kernel, cudaFuncAttributeMaxDynamicSharedMemorySize, GEMM_SMEM);
    cudaFuncSetAttribute(out_tc_kernel, cudaFuncAttributeMaxDynamicSharedMemorySize, GEMM_SMEM);
    cudaFuncSetAttribute(attn_tc_kernel, cudaFuncAttributeMaxDynamicSharedMemorySize, ATT_SMEM);

    const int W4 = NIN * NIN / 4;
    const int X4 = MTOT * NIN / 4;

    split_kernel<<<(X4 + 255) / 256, 256>>>(x,  xh, xl, X4);
    split_kernel<<<(W4 + 255) / 256, 256>>>(Wq, wh + 0 * NIN * NIN, wl + 0 * NIN * NIN, W4);
    split_kernel<<<(W4 + 255) / 256, 256>>>(Wk, wh + 1 * NIN * NIN, wl + 1 * NIN * NIN, W4);
    split_kernel<<<(W4 + 255) / 256, 256>>>(Wv, wh + 2 * NIN * NIN, wl + 2 * NIN * NIN, W4);
    split_kernel<<<(W4 + 255) / 256, 256>>>(Wo, wh + 3 * NIN * NIN, wl + 3 * NIN * NIN, W4);

    qkv_tc_kernel<<<dim3(NIN / 128, MTOT / 128, 3), 256, GEMM_SMEM>>>(bq, bk, bv);
    attn_tc_kernel<<<dim3(SEQ / 128, BH), 256, ATT_SMEM>>>();
    out_tc_kernel<<<dim3(NIN / 128, MTOT / 128), 256, GEMM_SMEM>>>(bo, out);
}